// round 3
// baseline (speedup 1.0000x reference)
#include <cuda_runtime.h>
#include <cuda_bf16.h>
#include <math.h>

#define N0 1000000
#define N1 67584
#define N2 6144
#define N3 1024
#define F_IN 100
#define HID 256
#define OUT 47
#define FAN1 15
#define FAN2 10
#define FAN3 5

// ---------------- scratch (device globals; no cudaMalloc allowed) -----------
__device__ float g_agg1[(size_t)N1 * F_IN];   // 27 MB
__device__ float g_h1  [(size_t)N1 * HID];    // 69 MB
__device__ float g_agg2[(size_t)N2 * HID];    // 6.3 MB
__device__ float g_h2  [(size_t)N2 * HID];    // 6.3 MB
__device__ float g_agg3[(size_t)N3 * HID];    // 1 MB
__device__ int   g_idx64;                     // 1 if index arrays are int64

// ---------------- index width probe ----------------------------------------
// dst1 = repeat(arange(N1), 15). If stored as int32, word 15 == 1.
// If stored as int64 (little endian), word 15 is the high half of element 7 == 0.
__global__ void probe_idx_kernel(const int* __restrict__ dst1) {
    if (threadIdx.x == 0) g_idx64 = (dst1[15] == 0) ? 1 : 0;
}

// ---------------- gather + mean: one warp per destination -------------------
template <int D, int FAN>
__global__ __launch_bounds__(128)
void gather_mean_kernel(const void* __restrict__ src_idx,
                        const float* __restrict__ X,
                        float* __restrict__ Agg, int n_dst) {
    int warp = (blockIdx.x * blockDim.x + threadIdx.x) >> 5;
    int lane = threadIdx.x & 31;
    if (warp >= n_dst) return;

    constexpr int NR = (D + 31) / 32;
    float acc[NR];
#pragma unroll
    for (int i = 0; i < NR; i++) acc[i] = 0.0f;

    const bool is64 = (g_idx64 != 0);
    const long base = (long)warp * FAN;
    const long long* __restrict__ s64 = (const long long*)src_idx;
    const int*       __restrict__ s32 = (const int*)src_idx;

#pragma unroll 4
    for (int e = 0; e < FAN; e++) {
        long s = is64 ? (long)s64[base + e] : (long)s32[base + e];
        const float* __restrict__ row = X + s * (long)D;
#pragma unroll
        for (int i = 0; i < NR; i++) {
            int c = lane + 32 * i;
            if (D % 32 == 0 || c < D) acc[i] += __ldg(row + c);
        }
    }
    const float inv = 1.0f / (float)FAN;
    float* __restrict__ out = Agg + (long)warp * D;
#pragma unroll
    for (int i = 0; i < NR; i++) {
        int c = lane + 32 * i;
        if (D % 32 == 0 || c < D) out[c] = acc[i] * inv;
    }
}

// ---------------- fused dual GEMM: C = act(A0@B0 + A1@B1 + bias) ------------
// A_p: [M, K_p] row-major (lda_p), B_p: [K_p, N] row-major, C: [M, N].
// M % 128 == 0, N % 128 == 0 required (holds for all call sites).
#define BM 128
#define BN 128
#define BK 16

__global__ __launch_bounds__(256)
void dual_gemm_kernel(const float* __restrict__ A0, const float* __restrict__ B0, int K0, int lda0,
                      const float* __restrict__ A1, const float* __restrict__ B1, int K1, int lda1,
                      const float* __restrict__ bias,
                      float* __restrict__ C, int M, int N, int do_relu) {
    __shared__ float As[BK][BM + 1];   // +1 pad: conflict-free transposed store
    __shared__ float Bs[BK][BN];

    const int tx = threadIdx.x & 15;   // column group
    const int ty = threadIdx.x >> 4;   // row group
    const int m0 = blockIdx.y * BM;
    const int n0 = blockIdx.x * BN;

    float acc[8][8];
#pragma unroll
    for (int i = 0; i < 8; i++)
#pragma unroll
        for (int j = 0; j < 8; j++) acc[i][j] = 0.0f;

    for (int p = 0; p < 2; p++) {
        const float* __restrict__ A = p ? A1 : A0;
        const float* __restrict__ B = p ? B1 : B0;
        const int K   = p ? K1 : K0;
        const int lda = p ? lda1 : lda0;

        for (int k0 = 0; k0 < K; k0 += BK) {
            // A tile: (row r, k) -> As[k][r].  tid: k = tid&15, r = tid>>4 (+16 each iter)
            {
                const int ka = threadIdx.x & 15;
                const int ra = threadIdx.x >> 4;
                const int kk = k0 + ka;
                const bool kv = (kk < K);
#pragma unroll
                for (int rr = 0; rr < 8; rr++) {
                    int r = ra + rr * 16;
                    float v = 0.0f;
                    if (kv) v = A[(long)(m0 + r) * lda + kk];
                    As[ka][r] = v;
                }
            }
            // B tile: (k, col n) -> Bs[k][n].  tid: n = tid&127, k = tid>>7 (+2 each iter)
            {
                const int nb  = threadIdx.x & 127;
                const int kb0 = threadIdx.x >> 7;
#pragma unroll
                for (int it = 0; it < 8; it++) {
                    int kk = kb0 + it * 2;
                    float v = 0.0f;
                    if (k0 + kk < K) v = B[(long)(k0 + kk) * N + n0 + nb];
                    Bs[kk][nb] = v;
                }
            }
            __syncthreads();

#pragma unroll
            for (int k = 0; k < BK; k++) {
                float ra_[8], rb_[8];
#pragma unroll
                for (int i = 0; i < 8; i++) ra_[i] = As[k][ty + 16 * i];
#pragma unroll
                for (int j = 0; j < 8; j++) rb_[j] = Bs[k][tx + 16 * j];
#pragma unroll
                for (int i = 0; i < 8; i++)
#pragma unroll
                    for (int j = 0; j < 8; j++) acc[i][j] += ra_[i] * rb_[j];
            }
            __syncthreads();
        }
    }

    // epilogue: bias + optional relu
#pragma unroll
    for (int j = 0; j < 8; j++) {
        const int n = n0 + tx + 16 * j;
        const float b = bias[n];
#pragma unroll
        for (int i = 0; i < 8; i++) {
            const int m = m0 + ty + 16 * i;
            float v = acc[i][j] + b;
            if (do_relu) v = fmaxf(v, 0.0f);
            C[(long)m * N + n] = v;
        }
    }
}

// ---------------- layer 3: dual GEMM (N=47) + log_softmax fused -------------
__global__ __launch_bounds__(64)
void out_layer_kernel(const float* __restrict__ A0,   // agg3 [N3, 256]
                      const float* __restrict__ A1,   // h2   [.., 256] (first N3 rows)
                      const float* __restrict__ Wl,   // [256, 47]
                      const float* __restrict__ Wr,   // [256, 47]
                      const float* __restrict__ bias, // [47]
                      float* __restrict__ out) {      // [N3, 47]
    const int m = blockIdx.x;
    __shared__ float sa[HID];
    __shared__ float sh[HID];
    __shared__ float logits[64];
    __shared__ float s_max, s_lse;

    for (int i = threadIdx.x; i < HID; i += blockDim.x) {
        sa[i] = A0[(long)m * HID + i];
        sh[i] = A1[(long)m * HID + i];
    }
    __syncthreads();

    const int n = threadIdx.x;
    if (n < OUT) {
        float s = bias[n];
#pragma unroll 8
        for (int k = 0; k < HID; k++) {
            s += sa[k] * Wl[k * OUT + n] + sh[k] * Wr[k * OUT + n];
        }
        logits[n] = s;
    }
    __syncthreads();

    if (threadIdx.x < 32) {
        float v1 = (threadIdx.x < OUT)      ? logits[threadIdx.x]      : -INFINITY;
        float v2 = (threadIdx.x + 32 < OUT) ? logits[threadIdx.x + 32] : -INFINITY;
        float mx = fmaxf(v1, v2);
#pragma unroll
        for (int o = 16; o > 0; o >>= 1) mx = fmaxf(mx, __shfl_xor_sync(0xFFFFFFFFu, mx, o));
        float e = 0.0f;
        if (threadIdx.x < OUT)      e += expf(v1 - mx);
        if (threadIdx.x + 32 < OUT) e += expf(v2 - mx);
#pragma unroll
        for (int o = 16; o > 0; o >>= 1) e += __shfl_xor_sync(0xFFFFFFFFu, e, o);
        if (threadIdx.x == 0) { s_max = mx; s_lse = logf(e); }
    }
    __syncthreads();

    if (n < OUT) out[(long)m * OUT + n] = logits[n] - s_max - s_lse;
}

// ---------------- launch ----------------------------------------------------
extern "C" void kernel_launch(void* const* d_in, const int* in_sizes, int n_in,
                              void* d_out, int out_size) {
    const float* x    = (const float*)d_in[0];
    const float* W_l1 = (const float*)d_in[1];
    const float* W_r1 = (const float*)d_in[2];
    const float* b1   = (const float*)d_in[3];
    const float* W_l2 = (const float*)d_in[4];
    const float* W_r2 = (const float*)d_in[5];
    const float* b2   = (const float*)d_in[6];
    const float* W_l3 = (const float*)d_in[7];
    const float* W_r3 = (const float*)d_in[8];
    const float* b3   = (const float*)d_in[9];
    const void*  src1 = d_in[10];
    const void*  dst1 = d_in[11];
    const void*  src2 = d_in[12];
    const void*  src3 = d_in[14];
    float* out = (float*)d_out;

    float* agg1; cudaGetSymbolAddress((void**)&agg1, g_agg1);
    float* h1;   cudaGetSymbolAddress((void**)&h1,   g_h1);
    float* agg2; cudaGetSymbolAddress((void**)&agg2, g_agg2);
    float* h2;   cudaGetSymbolAddress((void**)&h2,   g_h2);
    float* agg3; cudaGetSymbolAddress((void**)&agg3, g_agg3);

    // detect int32 vs int64 indices (deterministic, graph-capturable)
    probe_idx_kernel<<<1, 32>>>((const int*)dst1);

    // Layer 1
    gather_mean_kernel<F_IN, FAN1><<<N1 / 4, 128>>>(src1, x, agg1, N1);
    dual_gemm_kernel<<<dim3(HID / BN, N1 / BM), 256>>>(
        agg1, W_l1, F_IN, F_IN, x, W_r1, F_IN, F_IN, b1, h1, N1, HID, 1);

    // Layer 2
    gather_mean_kernel<HID, FAN2><<<N2 / 4, 128>>>(src2, h1, agg2, N2);
    dual_gemm_kernel<<<dim3(HID / BN, N2 / BM), 256>>>(
        agg2, W_l2, HID, HID, h1, W_r2, HID, HID, b2, h2, N2, HID, 1);

    // Layer 3 + log_softmax
    gather_mean_kernel<HID, FAN3><<<N3 / 4, 128>>>(src3, h2, agg3, N3);
    out_layer_kernel<<<N3, 64>>>(agg3, h2, W_l3, W_r3, b3, out);
}

// round 5
// speedup vs baseline: 1.1894x; 1.1894x over previous
#include <cuda_runtime.h>
#include <cuda_bf16.h>
#include <math.h>

#define N0 1000000
#define N1 67584
#define N2 6144
#define N3 1024
#define F_IN 100
#define HID 256
#define OUT 47
#define FAN1 15
#define FAN2 10
#define FAN3 5

// ---------------- scratch (device globals; no cudaMalloc allowed) -----------
__device__ float g_agg1[(size_t)N1 * F_IN];   // 27 MB
__device__ float g_h1  [(size_t)N1 * HID];    // 69 MB
__device__ float g_agg2[(size_t)N2 * HID];    // 6.3 MB
__device__ float g_h2  [(size_t)N2 * HID];    // 6.3 MB
__device__ float g_agg3[(size_t)N3 * HID];    // 1 MB
__device__ int   g_idx64;                     // 1 if index arrays are int64

// ---------------- index width probe ----------------------------------------
// dst1 = repeat(arange(N1), 15). int32 -> word 15 == 1; int64 -> word 15 == 0.
__global__ void probe_idx_kernel(const int* __restrict__ dst1) {
    if (threadIdx.x == 0) g_idx64 = (dst1[15] == 0) ? 1 : 0;
}

// ---------------- gather + mean: one warp per destination, float4 -----------
template <int D, int FAN, bool STREAM>
__global__ __launch_bounds__(128)
void gather_mean_kernel(const void* __restrict__ src_idx,
                        const float* __restrict__ X,
                        float* __restrict__ Agg, int n_dst) {
    const int warp = (blockIdx.x * blockDim.x + threadIdx.x) >> 5;
    const int lane = threadIdx.x & 31;
    if (warp >= n_dst) return;

    constexpr int D4 = D / 4;                 // 25 (D=100) or 64 (D=256)
    constexpr int NV = (D4 + 31) / 32;
    float4 acc[NV];
#pragma unroll
    for (int i = 0; i < NV; i++) acc[i] = make_float4(0.f, 0.f, 0.f, 0.f);

    const bool is64 = (g_idx64 != 0);
    const long base = (long)warp * FAN;
    const long long* __restrict__ s64 = (const long long*)src_idx;
    const int*       __restrict__ s32 = (const int*)src_idx;
    const float4* __restrict__ X4 = (const float4*)X;

#pragma unroll
    for (int e = 0; e < FAN; e++) {
        long s = is64 ? (long)s64[base + e] : (long)s32[base + e];
        const float4* __restrict__ row = X4 + s * (long)D4;
#pragma unroll
        for (int i = 0; i < NV; i++) {
            int c = lane + 32 * i;
            if ((D4 % 32 == 0) || c < D4) {
                float4 v = STREAM ? __ldcs(row + c) : __ldg(row + c);
                acc[i].x += v.x; acc[i].y += v.y; acc[i].z += v.z; acc[i].w += v.w;
            }
        }
    }
    const float inv = 1.0f / (float)FAN;
    float4* __restrict__ out = (float4*)(Agg + (long)warp * D);
#pragma unroll
    for (int i = 0; i < NV; i++) {
        int c = lane + 32 * i;
        if ((D4 % 32 == 0) || c < D4) {
            float4 v;
            v.x = acc[i].x * inv; v.y = acc[i].y * inv;
            v.z = acc[i].z * inv; v.w = acc[i].w * inv;
            out[c] = v;
        }
    }
}

// ---------------- bf16 split helpers ----------------------------------------
__device__ __forceinline__ void split_bf(float a, unsigned short& hi, unsigned short& lo) {
    __nv_bfloat16 h = __float2bfloat16(a);
    __nv_bfloat16 l = __float2bfloat16(a - __bfloat162float(h));
    hi = __bfloat16_as_ushort(h);
    lo = __bfloat16_as_ushort(l);
}
__device__ __forceinline__ unsigned pack2(unsigned short even, unsigned short odd) {
    return (unsigned)even | ((unsigned)odd << 16);
}

// ---------------- dual GEMM, bf16x3 tensor cores ----------------------------
// C = act(A0@B0 + A1@B1 + bias). A_p:[M,K_p] rm (lda_p), B_p:[K_p,N] rm, C:[M,N].
// M%128==0, N%128==0. Each fp32 operand split hi+lo bf16; 3 mma passes
// (hi*hi + hi*lo + lo*hi) -> ~2^-16 relative error, fp32 accumulate.
#define BM 128
#define BN 128
#define BK 16

__global__ __launch_bounds__(512, 1)
void dual_gemm_bf16_kernel(const float* __restrict__ A0, const float* __restrict__ B0, int K0, int lda0,
                           const float* __restrict__ A1, const float* __restrict__ B1, int K1, int lda1,
                           const float* __restrict__ bias,
                           float* __restrict__ C, int M, int N, int do_relu) {
    // smem: k-paired 32-bit words. As[m][kp] word = (A[m][2kp], A[m][2kp+1])
    //       Bs[kp][n] word = (B[2kp][n], B[2kp+1][n])
    __shared__ unsigned As_hi[BM][9], As_lo[BM][9];        // 8 kpairs + 1 pad
    __shared__ unsigned Bs_hi[8][BN + 4], Bs_lo[8][BN + 4];

    const int tid  = threadIdx.x;
    const int wid  = tid >> 5;
    const int lane = tid & 31;
    const int g    = lane >> 2;     // groupID (row/col within fragment)
    const int c    = lane & 3;      // thread-in-group (kpair index)
    const int wm   = wid & 3;       // warp row 0..3  (32 rows each)
    const int wn   = wid >> 2;      // warp col 0..3  (32 cols each)
    const int m0   = blockIdx.y * BM;
    const int n0   = blockIdx.x * BN;

    float acc[2][4][4];
#pragma unroll
    for (int mi = 0; mi < 2; mi++)
#pragma unroll
        for (int ni = 0; ni < 4; ni++)
#pragma unroll
            for (int q = 0; q < 4; q++) acc[mi][ni][q] = 0.0f;

    for (int p = 0; p < 2; p++) {
        const float* __restrict__ A = p ? A1 : A0;
        const float* __restrict__ B = p ? B1 : B0;
        const int K   = p ? K1 : K0;
        const int lda = p ? lda1 : lda0;

        for (int k0 = 0; k0 < K; k0 += BK) {
            // ---- load A tile: thread t -> row m=t>>2, kgroup=t&3 (4 floats) ----
            {
                const int m  = tid >> 2;
                const int kg = tid & 3;
                const int k  = k0 + 4 * kg;
                float4 v = make_float4(0.f, 0.f, 0.f, 0.f);
                if (k + 3 < K) {
                    v = *(const float4*)(A + (long)(m0 + m) * lda + k);
                } else {
                    const float* row = A + (long)(m0 + m) * lda;
                    if (k     < K) v.x = row[k];
                    if (k + 1 < K) v.y = row[k + 1];
                    if (k + 2 < K) v.z = row[k + 2];
                    if (k + 3 < K) v.w = row[k + 3];
                }
                unsigned short hx, lx, hy, ly, hz, lz, hw, lw;
                split_bf(v.x, hx, lx); split_bf(v.y, hy, ly);
                split_bf(v.z, hz, lz); split_bf(v.w, hw, lw);
                As_hi[m][2 * kg]     = pack2(hx, hy);
                As_lo[m][2 * kg]     = pack2(lx, ly);
                As_hi[m][2 * kg + 1] = pack2(hz, hw);
                As_lo[m][2 * kg + 1] = pack2(lz, lw);
            }
            // ---- load B tile: thread t -> n=t&127, kpg=t>>7; kp in {kpg, kpg+4} ----
            {
                const int n   = tid & 127;
                const int kpg = tid >> 7;
#pragma unroll
                for (int i = 0; i < 2; i++) {
                    const int kp = kpg + 4 * i;
                    const int ke = k0 + 2 * kp;
                    float b_e = 0.f, b_o = 0.f;
                    if (ke     < K) b_e = B[(long)ke * N + n0 + n];
                    if (ke + 1 < K) b_o = B[(long)(ke + 1) * N + n0 + n];
                    unsigned short he, le, ho, lo;
                    split_bf(b_e, he, le); split_bf(b_o, ho, lo);
                    Bs_hi[kp][n] = pack2(he, ho);
                    Bs_lo[kp][n] = pack2(le, lo);
                }
            }
            __syncthreads();

            // ---- fragments ----
            unsigned a_hi[2][4], a_lo[2][4], b_hi[4][2], b_lo[4][2];
#pragma unroll
            for (int mi = 0; mi < 2; mi++) {
                const int r = wm * 32 + mi * 16 + g;
                a_hi[mi][0] = As_hi[r][c];         a_lo[mi][0] = As_lo[r][c];
                a_hi[mi][1] = As_hi[r + 8][c];     a_lo[mi][1] = As_lo[r + 8][c];
                a_hi[mi][2] = As_hi[r][c + 4];     a_lo[mi][2] = As_lo[r][c + 4];
                a_hi[mi][3] = As_hi[r + 8][c + 4]; a_lo[mi][3] = As_lo[r + 8][c + 4];
            }
#pragma unroll
            for (int ni = 0; ni < 4; ni++) {
                const int col = wn * 32 + ni * 8 + g;
                b_hi[ni][0] = Bs_hi[c][col];     b_lo[ni][0] = Bs_lo[c][col];
                b_hi[ni][1] = Bs_hi[c + 4][col]; b_lo[ni][1] = Bs_lo[c + 4][col];
            }

            // ---- 3-pass mma: hi*hi + hi*lo + lo*hi ----
#pragma unroll
            for (int mi = 0; mi < 2; mi++) {
#pragma unroll
                for (int ni = 0; ni < 4; ni++) {
                    float* d = acc[mi][ni];
#define MMA_BF16(AF, BF)                                                         \
    asm volatile(                                                                \
        "mma.sync.aligned.m16n8k16.row.col.f32.bf16.bf16.f32 "                   \
        "{%0,%1,%2,%3}, {%4,%5,%6,%7}, {%8,%9}, {%0,%1,%2,%3};"                  \
        : "+f"(d[0]), "+f"(d[1]), "+f"(d[2]), "+f"(d[3])                         \
        : "r"(AF[0]), "r"(AF[1]), "r"(AF[2]), "r"(AF[3]), "r"(BF[0]), "r"(BF[1]))
                    MMA_BF16(a_hi[mi], b_hi[ni]);
                    MMA_BF16(a_hi[mi], b_lo[ni]);
                    MMA_BF16(a_lo[mi], b_hi[ni]);
#undef MMA_BF16
                }
            }
            __syncthreads();
        }
    }

    // ---- epilogue: bias + optional relu, float2 stores ----
#pragma unroll
    for (int mi = 0; mi < 2; mi++) {
#pragma unroll
        for (int ni = 0; ni < 4; ni++) {
            const int col = n0 + wn * 32 + ni * 8 + 2 * c;
            const float bv0 = bias[col], bv1 = bias[col + 1];
            const int r0 = m0 + wm * 32 + mi * 16 + g;
            float2 v;
            v.x = acc[mi][ni][0] + bv0;
            v.y = acc[mi][ni][1] + bv1;
            if (do_relu) { v.x = fmaxf(v.x, 0.f); v.y = fmaxf(v.y, 0.f); }
            *(float2*)(C + (long)r0 * N + col) = v;
            v.x = acc[mi][ni][2] + bv0;
            v.y = acc[mi][ni][3] + bv1;
            if (do_relu) { v.x = fmaxf(v.x, 0.f); v.y = fmaxf(v.y, 0.f); }
            *(float2*)(C + (long)(r0 + 8) * N + col) = v;
        }
    }
}

// ---------------- layer 3: dual GEMM (N=47) + log_softmax fused -------------
__global__ __launch_bounds__(64)
void out_layer_kernel(const float* __restrict__ A0,   // agg3 [N3, 256]
                      const float* __restrict__ A1,   // h2 first N3 rows
                      const float* __restrict__ Wl,   // [256, 47]
                      const float* __restrict__ Wr,   // [256, 47]
                      const float* __restrict__ bias, // [47]
                      float* __restrict__ out) {      // [N3, 47]
    const int m = blockIdx.x;
    __shared__ float sa[HID];
    __shared__ float sh[HID];
    __shared__ float logits[64];
    __shared__ float s_max, s_lse;

    for (int i = threadIdx.x; i < HID; i += blockDim.x) {
        sa[i] = A0[(long)m * HID + i];
        sh[i] = A1[(long)m * HID + i];
    }
    __syncthreads();

    const int n = threadIdx.x;
    if (n < OUT) {
        float s = bias[n];
#pragma unroll 8
        for (int k = 0; k < HID; k++) {
            s += sa[k] * Wl[k * OUT + n] + sh[k] * Wr[k * OUT + n];
        }
        logits[n] = s;
    }
    __syncthreads();

    if (threadIdx.x < 32) {
        float v1 = (threadIdx.x < OUT)      ? logits[threadIdx.x]      : -INFINITY;
        float v2 = (threadIdx.x + 32 < OUT) ? logits[threadIdx.x + 32] : -INFINITY;
        float mx = fmaxf(v1, v2);
#pragma unroll
        for (int o = 16; o > 0; o >>= 1) mx = fmaxf(mx, __shfl_xor_sync(0xFFFFFFFFu, mx, o));
        float e = 0.0f;
        if (threadIdx.x < OUT)      e += expf(v1 - mx);
        if (threadIdx.x + 32 < OUT) e += expf(v2 - mx);
#pragma unroll
        for (int o = 16; o > 0; o >>= 1) e += __shfl_xor_sync(0xFFFFFFFFu, e, o);
        if (threadIdx.x == 0) { s_max = mx; s_lse = logf(e); }
    }
    __syncthreads();

    if (n < OUT) out[(long)m * OUT + n] = logits[n] - s_max - s_lse;
}

// ---------------- launch ----------------------------------------------------
extern "C" void kernel_launch(void* const* d_in, const int* in_sizes, int n_in,
                              void* d_out, int out_size) {
    const float* x    = (const float*)d_in[0];
    const float* W_l1 = (const float*)d_in[1];
    const float* W_r1 = (const float*)d_in[2];
    const float* b1   = (const float*)d_in[3];
    const float* W_l2 = (const float*)d_in[4];
    const float* W_r2 = (const float*)d_in[5];
    const float* b2   = (const float*)d_in[6];
    const float* W_l3 = (const float*)d_in[7];
    const float* W_r3 = (const float*)d_in[8];
    const float* b3   = (const float*)d_in[9];
    const void*  src1 = d_in[10];
    const void*  dst1 = d_in[11];
    const void*  src2 = d_in[12];
    const void*  src3 = d_in[14];
    float* out = (float*)d_out;

    float* agg1; cudaGetSymbolAddress((void**)&agg1, g_agg1);
    float* h1;   cudaGetSymbolAddress((void**)&h1,   g_h1);
    float* agg2; cudaGetSymbolAddress((void**)&agg2, g_agg2);
    float* h2;   cudaGetSymbolAddress((void**)&h2,   g_h2);
    float* agg3; cudaGetSymbolAddress((void**)&agg3, g_agg3);

    probe_idx_kernel<<<1, 32>>>((const int*)dst1);

    // Layer 1
    gather_mean_kernel<F_IN, FAN1, true><<<N1 / 4, 128>>>(src1, x, agg1, N1);
    dual_gemm_bf16_kernel<<<dim3(HID / BN, N1 / BM), 512>>>(
        agg1, W_l1, F_IN, F_IN, x, W_r1, F_IN, F_IN, b1, h1, N1, HID, 1);

    // Layer 2
    gather_mean_kernel<HID, FAN2, false><<<N2 / 4, 128>>>(src2, h1, agg2, N2);
    dual_gemm_bf16_kernel<<<dim3(HID / BN, N2 / BM), 512>>>(
        agg2, W_l2, HID, HID, h1, W_r2, HID, HID, b2, h2, N2, HID, 1);

    // Layer 3 + log_softmax
    gather_mean_kernel<HID, FAN3, false><<<N3 / 4, 128>>>(src3, h2, agg3, N3);
    out_layer_kernel<<<N3, 64>>>(agg3, h2, W_l3, W_r3, b3, out);
}